// round 2
// baseline (speedup 1.0000x reference)
#include <cuda_runtime.h>
#include <cuda_fp16.h>
#include <cstdint>
#include <cfloat>

#define NPTS 1536
#define TLEN 20
#define HDIM 64
#define EDIM 16
#define MDIM 128
#define IPB  8            // i's per block (one per warp)
#define JC   32           // j rows per chunk
#define NCHUNK (NPTS / JC)

// padded row widths (in elements) for conflict-free smem access
#define APAD 136          // floats per A_s row
#define ZPAD 136          // halves per z row (272B -> row stride 68 words -> 4j banks)
#define WPAD 136          // halves per W2T row

// scratch (allocation-free rule: __device__ globals)
__device__ float g_A[NPTS * MDIM];
__device__ float g_B[NPTS * MDIM];

// ---------------------------------------------------------------------------
// Precompute: A[j,m] = hidden[j]@W1[:H] + end[j]@P + q + b1 ;  B[j,m] = end[j]@P
// grid = NPTS blocks, 128 threads (one per m)
// ---------------------------------------------------------------------------
__global__ void prep_kernel(const float* __restrict__ hidden,
                            const float* __restrict__ gt,
                            const float* __restrict__ We,
                            const float* __restrict__ be,
                            const float* __restrict__ W1,
                            const float* __restrict__ b1) {
    int j = blockIdx.x;
    int m = threadIdx.x;               // 0..127
    __shared__ float hs[HDIM];
    __shared__ float ev[2];
    if (m < HDIM) hs[m] = hidden[j * HDIM + m];
    if (m < 2)    ev[m] = gt[(j * TLEN + (TLEN - 1)) * 2 + m];
    __syncthreads();

    float p0 = 0.f, p1 = 0.f, q = 0.f;
#pragma unroll
    for (int e = 0; e < EDIM; e++) {
        float wv = W1[(HDIM + e) * MDIM + m];
        p0 += We[e] * wv;              // We row 0
        p1 += We[EDIM + e] * wv;       // We row 1
        q  += be[e] * wv;
    }
    float s = 0.f;
#pragma unroll 8
    for (int h = 0; h < HDIM; h++) s += hs[h] * W1[h * MDIM + m];

    float d = ev[0] * p0 + ev[1] * p1;
    g_B[j * MDIM + m] = d;
    g_A[j * MDIM + m] = s + d + q + b1[m];
}

// ---------------------------------------------------------------------------
// Main kernel: grid = NPTS/IPB blocks, 256 threads (8 warps, warp w -> i)
// out[i,h] = relu( max_j ( relu(A[j]-B[i]) @ W2 )[h] + b2[h] )
// ---------------------------------------------------------------------------
__global__ void __launch_bounds__(256, 2)
main_kernel(const float* __restrict__ W2, const float* __restrict__ b2,
            float* __restrict__ out) {
    extern __shared__ char smem_raw[];
    float* A_s = (float*)smem_raw;                          // [JC][APAD]   17408 B
    __half* z_s = (__half*)(smem_raw + JC * APAD * 4);      // [IPB][JC][ZPAD] 69632 B
    __half* w2t = (__half*)(smem_raw + JC * APAD * 4 + IPB * JC * ZPAD * 2); // [HDIM][WPAD] 17408 B

    const int tid  = threadIdx.x;
    const int w    = tid >> 5;
    const int lane = tid & 31;
    const int i    = blockIdx.x * IPB + w;

    // ---- stage W2^T (h-major) as fp16, conflict-free pad ----
    for (int idx = tid; idx < MDIM * HDIM; idx += 256) {
        int m = idx >> 6, h = idx & 63;                      // W2 is (M,H) row-major
        w2t[h * WPAD + m] = __float2half(W2[idx]);
    }

    // ---- B[i] in registers (4 regs) ----
    const float2 b_lo = *(const float2*)&g_B[i * MDIM + 2 * lane];
    const float2 b_hi = *(const float2*)&g_B[i * MDIM + 64 + 2 * lane];

    // running max: mx[ht][0] -> h = ht*8 + 2*(lane%4), mx[ht][1] -> +1
    float mx[8][2];
#pragma unroll
    for (int t = 0; t < 8; t++) { mx[t][0] = -FLT_MAX; mx[t][1] = -FLT_MAX; }

    // ldmatrix per-lane row addressing (x4: mats = [r0-7|c0], [r8-15|c0], [r0-7|c8], [r8-15|c8])
    const int mi   = lane >> 3;
    const int lrow = ((mi & 1) << 3) + (lane & 7);
    const int lcol = (mi >> 1) << 3;
    __half* zw = z_s + w * JC * ZPAD;

    for (int jc = 0; jc < NCHUNK; jc++) {
        __syncthreads();                                     // A_s reuse barrier
        // ---- stage A chunk: 32x128 f32, coalesced float4 ----
        const float4* Ag = (const float4*)(g_A + jc * JC * MDIM);
#pragma unroll
        for (int k = 0; k < 4; k++) {
            int idx4 = tid + k * 256;                        // 0..1023
            float4 v = Ag[idx4];
            int elem = idx4 << 2;
            int j = elem >> 7, m = elem & 127;
            *(float4*)&A_s[j * APAD + m] = v;
        }
        __syncthreads();

        // ---- z-gen: warp-private tile z[j][m] = relu(A[j][m]-B[i][m]) as fp16 ----
#pragma unroll 4
        for (int it = 0; it < 64; it++) {
            int j  = it >> 1;
            int hi = it & 1;
            int mq = hi * 32 + lane;                         // half2 index (m = 2*mq)
            float2 a = *(const float2*)&A_s[j * APAD + 2 * mq];
            float2 b = hi ? b_hi : b_lo;
            float z0 = fmaxf(a.x - b.x, 0.f);
            float z1 = fmaxf(a.y - b.y, 0.f);
            *(__half2*)&zw[j * ZPAD + 2 * mq] = __floats2half2_rn(z0, z1);
        }
        __syncwarp();

        // ---- MMA sweep: 2 j-tiles x 8 k-steps x 8 h-tiles ----
#pragma unroll
        for (int jt = 0; jt < 2; jt++) {
            float c[8][4];
#pragma unroll
            for (int t = 0; t < 8; t++) { c[t][0] = 0.f; c[t][1] = 0.f; c[t][2] = 0.f; c[t][3] = 0.f; }
#pragma unroll
            for (int ks = 0; ks < 8; ks++) {
                uint32_t a0, a1, a2, a3;
                uint32_t addr = (uint32_t)__cvta_generic_to_shared(
                    zw + (jt * 16 + lrow) * ZPAD + ks * 16 + lcol);
                asm volatile(
                    "ldmatrix.sync.aligned.m8n8.x4.shared.b16 {%0,%1,%2,%3}, [%4];"
                    : "=r"(a0), "=r"(a1), "=r"(a2), "=r"(a3) : "r"(addr));
                const int kk = ks * 16 + (lane & 3) * 2;
#pragma unroll
                for (int ht = 0; ht < 8; ht++) {
                    const int n = ht * 8 + (lane >> 2);
                    uint32_t b0 = *(const uint32_t*)&w2t[n * WPAD + kk];
                    uint32_t b1 = *(const uint32_t*)&w2t[n * WPAD + kk + 8];
                    asm volatile(
                        "mma.sync.aligned.m16n8k16.row.col.f32.f16.f16.f32 "
                        "{%0,%1,%2,%3},{%4,%5,%6,%7},{%8,%9},{%0,%1,%2,%3};"
                        : "+f"(c[ht][0]), "+f"(c[ht][1]), "+f"(c[ht][2]), "+f"(c[ht][3])
                        : "r"(a0), "r"(a1), "r"(a2), "r"(a3), "r"(b0), "r"(b1));
                }
            }
            // fold j (c rows) into running max
#pragma unroll
            for (int ht = 0; ht < 8; ht++) {
                mx[ht][0] = fmaxf(mx[ht][0], fmaxf(c[ht][0], c[ht][2]));
                mx[ht][1] = fmaxf(mx[ht][1], fmaxf(c[ht][1], c[ht][3]));
            }
        }
    }

    // ---- reduce max across lanes sharing the same h (lane%4 groups) ----
#pragma unroll
    for (int ht = 0; ht < 8; ht++) {
#pragma unroll
        for (int s = 4; s < 32; s <<= 1) {
            mx[ht][0] = fmaxf(mx[ht][0], __shfl_xor_sync(0xffffffffu, mx[ht][0], s));
            mx[ht][1] = fmaxf(mx[ht][1], __shfl_xor_sync(0xffffffffu, mx[ht][1], s));
        }
    }
    if (lane < 4) {
#pragma unroll
        for (int ht = 0; ht < 8; ht++) {
            int h = ht * 8 + 2 * lane;
            float2 o;
            o.x = fmaxf(mx[ht][0] + b2[h], 0.f);
            o.y = fmaxf(mx[ht][1] + b2[h + 1], 0.f);
            *(float2*)&out[i * HDIM + h] = o;
        }
    }
}

// ---------------------------------------------------------------------------
extern "C" void kernel_launch(void* const* d_in, const int* in_sizes, int n_in,
                              void* d_out, int out_size) {
    const float* hidden = (const float*)d_in[0];
    const float* gt     = (const float*)d_in[1];
    const float* We     = (const float*)d_in[2];
    const float* be     = (const float*)d_in[3];
    const float* W1     = (const float*)d_in[4];
    const float* b1     = (const float*)d_in[5];
    const float* W2     = (const float*)d_in[6];
    const float* b2     = (const float*)d_in[7];
    float* out = (float*)d_out;

    prep_kernel<<<NPTS, MDIM>>>(hidden, gt, We, be, W1, b1);

    const int smem = JC * APAD * 4 + IPB * JC * ZPAD * 2 + HDIM * WPAD * 2; // 104448
    cudaFuncSetAttribute(main_kernel, cudaFuncAttributeMaxDynamicSharedMemorySize, smem);
    main_kernel<<<NPTS / IPB, 256, smem>>>(W2, b2, out);
}

// round 3
// speedup vs baseline: 1.9034x; 1.9034x over previous
#include <cuda_runtime.h>
#include <cuda_fp16.h>
#include <cstdint>
#include <cfloat>

#define NPTS 1536
#define TLEN 20
#define HDIM 64
#define EDIM 16
#define MDIM 128
#define IPB  4            // i's per block
#define JC   32           // j rows per chunk
#define NCHUNK 48
#define JSPLIT 3          // j-range splits (blocks per i-group)
#define CPB (NCHUNK / JSPLIT)   // 16 chunks per block
#define APITCH 136        // halves per A_s row (pitch 68 words == 4 mod 32 -> conflict-free frags)

// scratch (__device__ globals: allocation-free rule)
__device__ __half g_Ah[NPTS * MDIM];
__device__ __half g_Bh[NPTS * MDIM];

// ---------------------------------------------------------------------------
// Precompute: A[j,m] = hidden[j]@W1[:H] + end[j]@P + q + b1 ;  B[j,m] = end[j]@P
// grid = NPTS, 128 threads (one per m). Stores fp16.
// ---------------------------------------------------------------------------
__global__ void prep_kernel(const float* __restrict__ hidden,
                            const float* __restrict__ gt,
                            const float* __restrict__ We,
                            const float* __restrict__ be,
                            const float* __restrict__ W1,
                            const float* __restrict__ b1) {
    int j = blockIdx.x;
    int m = threadIdx.x;               // 0..127
    __shared__ float hs[HDIM];
    __shared__ float ev[2];
    if (m < HDIM) hs[m] = hidden[j * HDIM + m];
    if (m < 2)    ev[m] = gt[(j * TLEN + (TLEN - 1)) * 2 + m];
    __syncthreads();

    float p0 = 0.f, p1 = 0.f, q = 0.f;
#pragma unroll
    for (int e = 0; e < EDIM; e++) {
        float wv = W1[(HDIM + e) * MDIM + m];
        p0 += We[e] * wv;
        p1 += We[EDIM + e] * wv;
        q  += be[e] * wv;
    }
    float s = 0.f;
#pragma unroll 8
    for (int h = 0; h < HDIM; h++) s += hs[h] * W1[h * MDIM + m];

    float d = ev[0] * p0 + ev[1] * p1;
    g_Bh[j * MDIM + m] = __float2half(d);
    g_Ah[j * MDIM + m] = __float2half(s + d + q + b1[m]);
}

// ---------------------------------------------------------------------------
// Main: grid = (NPTS/IPB)*JSPLIT = 1152 blocks, 256 threads (8 warps).
// warp w: i = ig*4 + (w>>1), h-slice = (w&1)*32.
// Fragment-direct z: A-fragments loaded from smem A chunk, subtract B (regs),
// relu in half2, feed mma.sync m16n8k16. Max folds in regs; j-partials merged
// into out via atomicMax on non-negative floats (relu output), out pre-zeroed.
// ---------------------------------------------------------------------------
__global__ void __launch_bounds__(256, 2)
main_kernel(const float* __restrict__ W2, const float* __restrict__ b2,
            float* __restrict__ out) {
    __shared__ __align__(16) __half A_s[2][JC * APITCH];   // 2 x 8704 B
    __shared__ __align__(16) __half w2t[HDIM * APITCH];    // 17408 B

    const int tid  = threadIdx.x;
    const int w    = tid >> 5;
    const int lane = tid & 31;
    const int ig   = blockIdx.x / JSPLIT;
    const int js   = blockIdx.x % JSPLIT;
    const int i    = ig * IPB + (w >> 1);
    const int wh   = w & 1;            // h-half
    const int jc0  = js * CPB;

    const int arow  = lane >> 2;       // 0..7
    const int acol2 = lane & 3;        // 0..3

    // ---- stage W2^T (h-major fp16, padded) ----
    for (int idx = tid; idx < MDIM * HDIM; idx += 256) {
        int m = idx >> 6, h = idx & 63;                    // W2 (M,H) row-major
        w2t[h * APITCH + m] = __float2half(W2[idx]);
    }

    // ---- B[i] fragments: bf[ks][p] = B_h2 at m/2 = ks*8 + p*4 + acol2 ----
    const __half2* Bh2 = (const __half2*)(g_Bh + i * MDIM);
    __half2 bf[8][2];
#pragma unroll
    for (int ks = 0; ks < 8; ks++) {
        bf[ks][0] = Bh2[ks * 8 + acol2];
        bf[ks][1] = Bh2[ks * 8 + 4 + acol2];
    }

    // ---- cp.async stage of first chunk ----
    auto stage = [&](int buf, int jc) {
        const __half* src_base = g_Ah + jc * JC * MDIM;
#pragma unroll
        for (int t = 0; t < 2; t++) {
            int idx = tid + t * 256;                       // 0..511 (16B segs)
            int row = idx >> 4, seg = idx & 15;
            uint32_t dst = (uint32_t)__cvta_generic_to_shared(
                &A_s[buf][row * APITCH + seg * 8]);
            const __half* src = src_base + row * MDIM + seg * 8;
            asm volatile("cp.async.ca.shared.global [%0], [%1], 16;"
                         :: "r"(dst), "l"(src) : "memory");
        }
        asm volatile("cp.async.commit_group;" ::: "memory");
    };
    stage(0, jc0);

    float mx[4][2];
#pragma unroll
    for (int t = 0; t < 4; t++) { mx[t][0] = -FLT_MAX; mx[t][1] = -FLT_MAX; }

    const __half2 zero2 = __floats2half2_rn(0.f, 0.f);

    for (int c = 0; c < CPB; c++) {
        if (c + 1 < CPB) {
            stage((c + 1) & 1, jc0 + c + 1);
            asm volatile("cp.async.wait_group 1;" ::: "memory");
        } else {
            asm volatile("cp.async.wait_group 0;" ::: "memory");
        }
        __syncthreads();

        const __half2* As2 = (const __half2*)A_s[c & 1];   // pitch 68 half2
        float cacc[2][4][4];
#pragma unroll
        for (int jt = 0; jt < 2; jt++)
#pragma unroll
            for (int ht = 0; ht < 4; ht++)
#pragma unroll
                for (int r = 0; r < 4; r++) cacc[jt][ht][r] = 0.f;

#pragma unroll
        for (int ks = 0; ks < 8; ks++) {
            // W2 fragments for 4 h-tiles
            uint32_t wb0[4], wb1[4];
            const int kk = ks * 16 + acol2 * 2;
#pragma unroll
            for (int ht = 0; ht < 4; ht++) {
                const int n = wh * 32 + ht * 8 + arow;
                wb0[ht] = *(const uint32_t*)&w2t[n * APITCH + kk];
                wb1[ht] = *(const uint32_t*)&w2t[n * APITCH + kk + 8];
            }
#pragma unroll
            for (int jt = 0; jt < 2; jt++) {
                const __half2* p = As2 + (jt * 16 + arow) * 68 + ks * 8 + acol2;
                __half2 v00 = p[0], v10 = p[544], v01 = p[4], v11 = p[548];
                __half2 a0h = __hmax2(__hsub2(v00, bf[ks][0]), zero2);
                __half2 a1h = __hmax2(__hsub2(v10, bf[ks][0]), zero2);
                __half2 a2h = __hmax2(__hsub2(v01, bf[ks][1]), zero2);
                __half2 a3h = __hmax2(__hsub2(v11, bf[ks][1]), zero2);
                uint32_t a0 = *(uint32_t*)&a0h, a1 = *(uint32_t*)&a1h;
                uint32_t a2 = *(uint32_t*)&a2h, a3 = *(uint32_t*)&a3h;
#pragma unroll
                for (int ht = 0; ht < 4; ht++) {
                    asm volatile(
                        "mma.sync.aligned.m16n8k16.row.col.f32.f16.f16.f32 "
                        "{%0,%1,%2,%3},{%4,%5,%6,%7},{%8,%9},{%0,%1,%2,%3};"
                        : "+f"(cacc[jt][ht][0]), "+f"(cacc[jt][ht][1]),
                          "+f"(cacc[jt][ht][2]), "+f"(cacc[jt][ht][3])
                        : "r"(a0), "r"(a1), "r"(a2), "r"(a3),
                          "r"(wb0[ht]), "r"(wb1[ht]));
                }
            }
        }
        // fold j-rows into running max
#pragma unroll
        for (int jt = 0; jt < 2; jt++)
#pragma unroll
            for (int ht = 0; ht < 4; ht++) {
                mx[ht][0] = fmaxf(mx[ht][0], fmaxf(cacc[jt][ht][0], cacc[jt][ht][2]));
                mx[ht][1] = fmaxf(mx[ht][1], fmaxf(cacc[jt][ht][1], cacc[jt][ht][3]));
            }
        __syncthreads();
    }

    // ---- reduce max across j-row groups (lanes differing in lane>>2) ----
#pragma unroll
    for (int ht = 0; ht < 4; ht++) {
#pragma unroll
        for (int s = 4; s < 32; s <<= 1) {
            mx[ht][0] = fmaxf(mx[ht][0], __shfl_xor_sync(0xffffffffu, mx[ht][0], s));
            mx[ht][1] = fmaxf(mx[ht][1], __shfl_xor_sync(0xffffffffu, mx[ht][1], s));
        }
    }
    if (lane < 4) {
#pragma unroll
        for (int ht = 0; ht < 4; ht++) {
            int h = wh * 32 + ht * 8 + 2 * lane;
            float v0 = fmaxf(mx[ht][0] + b2[h], 0.f);
            float v1 = fmaxf(mx[ht][1] + b2[h + 1], 0.f);
            // non-negative floats order as ints; out pre-zeroed
            atomicMax((int*)&out[i * HDIM + h],     __float_as_int(v0));
            atomicMax((int*)&out[i * HDIM + h + 1], __float_as_int(v1));
        }
    }
}

// ---------------------------------------------------------------------------
extern "C" void kernel_launch(void* const* d_in, const int* in_sizes, int n_in,
                              void* d_out, int out_size) {
    const float* hidden = (const float*)d_in[0];
    const float* gt     = (const float*)d_in[1];
    const float* We     = (const float*)d_in[2];
    const float* be     = (const float*)d_in[3];
    const float* W1     = (const float*)d_in[4];
    const float* b1     = (const float*)d_in[5];
    const float* W2     = (const float*)d_in[6];
    const float* b2     = (const float*)d_in[7];
    float* out = (float*)d_out;

    prep_kernel<<<NPTS, MDIM>>>(hidden, gt, We, be, W1, b1);
    cudaMemsetAsync(out, 0, (size_t)NPTS * HDIM * sizeof(float));
    main_kernel<<<(NPTS / IPB) * JSPLIT, 256>>>(W2, b2, out);
}

// round 4
// speedup vs baseline: 2.2418x; 1.1777x over previous
#include <cuda_runtime.h>
#include <cuda_fp16.h>
#include <cstdint>
#include <cfloat>

#define NPTS 1536
#define TLEN 20
#define HDIM 64
#define EDIM 16
#define MDIM 128
#define IPB  8              // i's per block (one per warp)
#define JC   32             // j rows per chunk
#define NCHUNK 48
#define JSPLIT 3            // j-range splits
#define CPB (NCHUNK / JSPLIT)
#define APITCH 144          // halves per smem row (72 words == 8 mod 32: LDS.64 conflict-free)

// scratch (__device__ globals: allocation-free rule). Stored k-PERMUTED (see mperm).
__device__ __half g_Ah[NPTS * MDIM];
__device__ __half g_Bh[NPTS * MDIM];

// Permutation within each 16-k group so mma fragment halves are contiguous:
// logical order per group: [0,1,8,9, 2,3,10,11, 4,5,12,13, 6,7,14,15]
__host__ __device__ __forceinline__ int mperm(int m) {
    int g = m >> 4, w = m & 15;
    int pos = (w < 8) ? ((w >> 1) * 4 + (w & 1))
                      : (((w - 8) >> 1) * 4 + 2 + (w & 1));
    return g * 16 + pos;
}

// ---------------------------------------------------------------------------
// Precompute: A[j,m] = hidden[j]@W1[:H] + end[j]@P + q + b1 ;  B[j,m] = end[j]@P
// grid = NPTS, 128 threads (one per m). Writes fp16, k-permuted.
// ---------------------------------------------------------------------------
__global__ void prep_kernel(const float* __restrict__ hidden,
                            const float* __restrict__ gt,
                            const float* __restrict__ We,
                            const float* __restrict__ be,
                            const float* __restrict__ W1,
                            const float* __restrict__ b1) {
    int j = blockIdx.x;
    int m = threadIdx.x;               // 0..127
    __shared__ float hs[HDIM];
    __shared__ float ev[2];
    if (m < HDIM) hs[m] = hidden[j * HDIM + m];
    if (m < 2)    ev[m] = gt[(j * TLEN + (TLEN - 1)) * 2 + m];
    __syncthreads();

    float p0 = 0.f, p1 = 0.f, q = 0.f;
#pragma unroll
    for (int e = 0; e < EDIM; e++) {
        float wv = W1[(HDIM + e) * MDIM + m];
        p0 += We[e] * wv;
        p1 += We[EDIM + e] * wv;
        q  += be[e] * wv;
    }
    float s = 0.f;
#pragma unroll 8
    for (int h = 0; h < HDIM; h++) s += hs[h] * W1[h * MDIM + m];

    float d = ev[0] * p0 + ev[1] * p1;
    int mp = mperm(m);
    g_Bh[j * MDIM + mp] = __float2half(d);
    g_Ah[j * MDIM + mp] = __float2half(s + d + q + b1[m]);
}

// ---------------------------------------------------------------------------
// Main: grid = (NPTS/IPB)*JSPLIT = 576 blocks, 256 threads (8 warps).
// warp w -> i = ig*8 + w, covers ALL 64 h (8 ht tiles) and 32 j per chunk.
// Fragment-direct z (regs), every fragment load is one LDS.64.
// ---------------------------------------------------------------------------
__global__ void __launch_bounds__(256, 2)
main_kernel(const float* __restrict__ W2, const float* __restrict__ b2,
            float* __restrict__ out) {
    __shared__ __align__(16) __half A_s[2][JC * APITCH];   // 2 x 9216 B
    __shared__ __align__(16) __half w2t[HDIM * APITCH];    // 18432 B

    const int tid  = threadIdx.x;
    const int w    = tid >> 5;
    const int lane = tid & 31;
    const int ig   = blockIdx.x / JSPLIT;
    const int js   = blockIdx.x % JSPLIT;
    const int i    = ig * IPB + w;
    const int jc0  = js * CPB;

    const int fr = lane >> 2;          // fragment row / n-index (0..7)
    const int fc = lane & 3;           // fragment k-quad (0..3)

    // ---- stage W2^T (h-major fp16, k-permuted) ----
    for (int idx = tid; idx < MDIM * HDIM; idx += 256) {
        int m = idx >> 6, h = idx & 63;                    // W2 (M,H) row-major
        w2t[h * APITCH + mperm(m)] = __float2half(W2[idx]);
    }

    // ---- B[i] fragments (permuted: 4 contiguous halves per ks) ----
    __half2 bf[8][2];
#pragma unroll
    for (int ks = 0; ks < 8; ks++) {
        uint2 bv = *(const uint2*)&g_Bh[i * MDIM + ks * 16 + fc * 4];
        bf[ks][0] = *(__half2*)&bv.x;
        bf[ks][1] = *(__half2*)&bv.y;
    }

    // ---- cp.async staging ----
    auto stage = [&](int buf, int jc) {
        const __half* src_base = g_Ah + jc * JC * MDIM;
#pragma unroll
        for (int t = 0; t < 2; t++) {
            int idx = tid + t * 256;                       // 0..511 (16B segs)
            int row = idx >> 4, seg = idx & 15;
            uint32_t dst = (uint32_t)__cvta_generic_to_shared(
                &A_s[buf][row * APITCH + seg * 8]);
            const __half* src = src_base + row * MDIM + seg * 8;
            asm volatile("cp.async.ca.shared.global [%0], [%1], 16;"
                         :: "r"(dst), "l"(src) : "memory");
        }
        asm volatile("cp.async.commit_group;" ::: "memory");
    };
    stage(0, jc0);

    float mx[8][2];
#pragma unroll
    for (int t = 0; t < 8; t++) { mx[t][0] = -FLT_MAX; mx[t][1] = -FLT_MAX; }

    const __half2 zero2 = __floats2half2_rn(0.f, 0.f);

    for (int c = 0; c < CPB; c++) {
        if (c + 1 < CPB) {
            stage((c + 1) & 1, jc0 + c + 1);
            asm volatile("cp.async.wait_group 1;" ::: "memory");
        } else {
            asm volatile("cp.async.wait_group 0;" ::: "memory");
        }
        __syncthreads();

        const __half* As = A_s[c & 1];
        float cacc[2][8][4];
#pragma unroll
        for (int jt = 0; jt < 2; jt++)
#pragma unroll
            for (int ht = 0; ht < 8; ht++)
#pragma unroll
                for (int r = 0; r < 4; r++) cacc[jt][ht][r] = 0.f;

#pragma unroll
        for (int ks = 0; ks < 8; ks++) {
            const int koff = ks * 16 + fc * 4;
            // z fragments for both j-tiles: 2 LDS.64 each, sub+relu in half2
            uint32_t za[2][4];
#pragma unroll
            for (int jt = 0; jt < 2; jt++) {
                uint2 v0 = *(const uint2*)&As[(jt * 16 + fr) * APITCH + koff];     // a0|a2
                uint2 v1 = *(const uint2*)&As[(jt * 16 + 8 + fr) * APITCH + koff]; // a1|a3
                __half2 a0 = __hmax2(__hsub2(*(__half2*)&v0.x, bf[ks][0]), zero2);
                __half2 a2 = __hmax2(__hsub2(*(__half2*)&v0.y, bf[ks][1]), zero2);
                __half2 a1 = __hmax2(__hsub2(*(__half2*)&v1.x, bf[ks][0]), zero2);
                __half2 a3 = __hmax2(__hsub2(*(__half2*)&v1.y, bf[ks][1]), zero2);
                za[jt][0] = *(uint32_t*)&a0;
                za[jt][1] = *(uint32_t*)&a1;
                za[jt][2] = *(uint32_t*)&a2;
                za[jt][3] = *(uint32_t*)&a3;
            }
#pragma unroll
            for (int ht = 0; ht < 8; ht++) {
                uint2 wb = *(const uint2*)&w2t[(ht * 8 + fr) * APITCH + koff];     // b0|b1
#pragma unroll
                for (int jt = 0; jt < 2; jt++) {
                    asm volatile(
                        "mma.sync.aligned.m16n8k16.row.col.f32.f16.f16.f32 "
                        "{%0,%1,%2,%3},{%4,%5,%6,%7},{%8,%9},{%0,%1,%2,%3};"
                        : "+f"(cacc[jt][ht][0]), "+f"(cacc[jt][ht][1]),
                          "+f"(cacc[jt][ht][2]), "+f"(cacc[jt][ht][3])
                        : "r"(za[jt][0]), "r"(za[jt][1]), "r"(za[jt][2]), "r"(za[jt][3]),
                          "r"(wb.x), "r"(wb.y));
                }
            }
        }
        // fold j-rows into running max
#pragma unroll
        for (int jt = 0; jt < 2; jt++)
#pragma unroll
            for (int ht = 0; ht < 8; ht++) {
                mx[ht][0] = fmaxf(mx[ht][0], fmaxf(cacc[jt][ht][0], cacc[jt][ht][2]));
                mx[ht][1] = fmaxf(mx[ht][1], fmaxf(cacc[jt][ht][1], cacc[jt][ht][3]));
            }
        __syncthreads();
    }

    // ---- reduce max across j-row groups (lanes differing in lane>>2) ----
#pragma unroll
    for (int ht = 0; ht < 8; ht++) {
#pragma unroll
        for (int s = 4; s < 32; s <<= 1) {
            mx[ht][0] = fmaxf(mx[ht][0], __shfl_xor_sync(0xffffffffu, mx[ht][0], s));
            mx[ht][1] = fmaxf(mx[ht][1], __shfl_xor_sync(0xffffffffu, mx[ht][1], s));
        }
    }
    if (lane < 4) {
#pragma unroll
        for (int ht = 0; ht < 8; ht++) {
            int h = ht * 8 + 2 * lane;
            float v0 = fmaxf(mx[ht][0] + b2[h], 0.f);
            float v1 = fmaxf(mx[ht][1] + b2[h + 1], 0.f);
            // relu outputs are >= 0: int-ordered atomicMax is exact; out pre-zeroed
            atomicMax((int*)&out[i * HDIM + h],     __float_as_int(v0));
            atomicMax((int*)&out[i * HDIM + h + 1], __float_as_int(v1));
        }
    }
}

// ---------------------------------------------------------------------------
extern "C" void kernel_launch(void* const* d_in, const int* in_sizes, int n_in,
                              void* d_out, int out_size) {
    const float* hidden = (const float*)d_in[0];
    const float* gt     = (const float*)d_in[1];
    const float* We     = (const float*)d_in[2];
    const float* be     = (const float*)d_in[3];
    const float* W1     = (const float*)d_in[4];
    const float* b1     = (const float*)d_in[5];
    const float* W2     = (const float*)d_in[6];
    const float* b2     = (const float*)d_in[7];
    float* out = (float*)d_out;

    prep_kernel<<<NPTS, MDIM>>>(hidden, gt, We, be, W1, b1);
    cudaMemsetAsync(out, 0, (size_t)NPTS * HDIM * sizeof(float));
    main_kernel<<<(NPTS / IPB) * JSPLIT, 256>>>(W2, b2, out);
}